// round 12
// baseline (speedup 1.0000x reference)
#include <cuda_runtime.h>
#include <cstdint>

// EdgeFeature: B=4, D=64, N=4096, K=16
// out = [ edge_feature (4,128,4096,16) fp32 ; idx (4,65536) as fp32 ]

#define B_ 4
#define D_ 64
#define N_ 4096
#define K_ 16

// Scratch (static __device__ — no allocations allowed in kernel_launch)
__device__ float g_sq[B_ * N_];                       // 64 KB
__device__ float g_dist[(size_t)B_ * N_ * N_];        // 256 MB
__device__ int   g_idx[B_ * N_ * K_];                 // 1 MB

// packed f32x2 FMA: both lanes are independent IEEE fp32 FMAs -> bitwise
// identical to scalar fmaf chains (validated rel_err==0 across rounds).
__device__ __forceinline__ void fma2(unsigned long long& c,
                                     unsigned long long a, unsigned long long b) {
    asm("fma.rn.f32x2 %0, %1, %2, %0;" : "+l"(c) : "l"(a), "l"(b));
}

__device__ __forceinline__ uint32_t smem_u32(const void* p) {
    uint32_t a;
    asm("{ .reg .u64 t; cvta.to.shared.u64 t, %1; cvt.u32.u64 %0, t; }"
        : "=r"(a) : "l"(p));
    return a;
}
__device__ __forceinline__ void cpasync16(uint32_t saddr, const void* g) {
    asm volatile("cp.async.ca.shared.global [%0], [%1], 16;"
                 :: "r"(saddr), "l"(g) : "memory");
}
__device__ __forceinline__ void cpcommit() {
    asm volatile("cp.async.commit_group;" ::: "memory");
}
template <int N>
__device__ __forceinline__ void cpwait() {
    asm volatile("cp.async.wait_group %0;" :: "n"(N) : "memory");
}

// ---------------------------------------------------------------------------
// 1) squared norms (sequential ascending d, fmaf — matches the GEMM's dot
//    accumulation order so self-distance cancels to exactly 0.0f)
// ---------------------------------------------------------------------------
__global__ void sq_kernel(const float* __restrict__ pc) {
    int gid = blockIdx.x * blockDim.x + threadIdx.x;
    int b = gid >> 12;
    int n = gid & (N_ - 1);
    const float* X = pc + (size_t)b * D_ * N_;
    float acc = 0.0f;
    #pragma unroll
    for (int d = 0; d < D_; d++) {
        float v = X[d * N_ + n];
        acc = fmaf(v, v, acc);
    }
    g_sq[gid] = acc;
}

// ---------------------------------------------------------------------------
// 2) dist = sqrt(max(sq_i + sq_j - 2*dot, 0)). UPPER-TRIANGLE tiles (528/b).
//    R11 FFMA2 mainloop + NEW: cp.async double-buffered K-chunks (4 chunks of
//    16, 2 buffers) so loads overlap compute — we are RF-capped at 16 warps/SM
//    so exposed load phases were pure stall. Mirror tile stored via the proven
//    smem-staged transpose (pitch 129), reusing the buffer pool.
// ---------------------------------------------------------------------------
#define BUFSTRIDE 4160            // floats per buffer (A 2048 | B 2048 | pad)

__global__ __launch_bounds__(256, 2) void d2_kernel(const float* __restrict__ pc) {
    __shared__ float pool[8400];  // 2 buffers @4160; reused as 64x129 stage
    __shared__ float sqa[128];
    __shared__ float sqb[128];

    int b = blockIdx.z;
    // decode linear tile id -> (by, bx) with bx >= by  (528 tiles)
    int tl = blockIdx.x;
    int by = 0;
    #pragma unroll 1
    while (tl >= 32 - by) { tl -= 32 - by; by++; }
    int bx = by + tl;

    int i0 = by * 128;
    int j0 = bx * 128;
    const float* X = pc + (size_t)b * D_ * N_;
    int t = threadIdx.x;

    if (t < 128) sqa[t]       = g_sq[b * N_ + i0 + t];
    else         sqb[t - 128] = g_sq[b * N_ + j0 + (t - 128)];

    int r = t >> 4;    // 0..15 row group
    int c = t & 15;    // 0..15 col group
    uint32_t pbase = smem_u32(pool);

    unsigned long long acc2[8][4];   // [row][col-pair]
    #pragma unroll
    for (int ii = 0; ii < 8; ii++)
        #pragma unroll
        for (int q = 0; q < 4; q++) acc2[ii][q] = 0ull;

    // issue chunk k (16 d-rows of A and B) into buffer k&1 via cp.async
    auto issue = [&](int k) {
        int dc  = k * 16;
        int buf = (k & 1) * BUFSTRIDE;
        #pragma unroll
        for (int l0 = 0; l0 < 1024; l0 += 256) {   // 4 x 16B per thread
            int l   = l0 + t;
            int isB = (l >= 512);
            int ll  = l - (isB << 9);
            int d   = ll >> 5;
            int i4  = (ll & 31) << 2;
            const float* g = X + (size_t)(dc + d) * N_ + (isB ? j0 : i0) + i4;
            uint32_t s = pbase + (uint32_t)(buf + (isB ? 2048 : 0) + d * 128 + i4) * 4u;
            cpasync16(s, g);
        }
        cpcommit();
    };

    issue(0);
    issue(1);

    #pragma unroll
    for (int k = 0; k < 4; k++) {
        if (k < 3) cpwait<1>(); else cpwait<0>();
        __syncthreads();
        const float* A = pool + (k & 1) * BUFSTRIDE;
        const float* Bp = A + 2048;
        #pragma unroll
        for (int d = 0; d < 16; d++) {
            float af[8];
            *(float4*)&af[0] = *(const float4*)&A[d * 128 + r * 8];
            *(float4*)&af[4] = *(const float4*)&A[d * 128 + r * 8 + 4];
            ulonglong2 B0 = *(const ulonglong2*)&Bp[d * 128 + c * 8];
            ulonglong2 B1 = *(const ulonglong2*)&Bp[d * 128 + c * 8 + 4];
            unsigned long long bp[4] = {B0.x, B0.y, B1.x, B1.y};
            unsigned long long ap[8];
            #pragma unroll
            for (int ii = 0; ii < 8; ii++)
                asm("mov.b64 %0, {%1, %1};" : "=l"(ap[ii]) : "f"(af[ii]));
            #pragma unroll
            for (int ii = 0; ii < 8; ii++)
                #pragma unroll
                for (int q = 0; q < 4; q++)
                    fma2(acc2[ii][q], ap[ii], bp[q]);
        }
        __syncthreads();                 // all warps done reading this buffer
        if (k + 2 < 4) issue(k + 2);     // refill it for chunk k+2
    }

    // normal store: rows i0.., cols j0.. (coalesced float4)
    #pragma unroll
    for (int ii = 0; ii < 8; ii++) {
        float si = sqa[r * 8 + ii];
        float v[8];
        #pragma unroll
        for (int q = 0; q < 4; q++) {
            float dx = __uint_as_float((unsigned)acc2[ii][q]);
            float dy = __uint_as_float((unsigned)(acc2[ii][q] >> 32));
            float s0 = si + sqb[c * 8 + 2 * q];
            float s1 = si + sqb[c * 8 + 2 * q + 1];
            v[2 * q]     = sqrtf(fmaxf(s0 - 2.0f * dx, 0.0f));
            v[2 * q + 1] = sqrtf(fmaxf(s1 - 2.0f * dy, 0.0f));
        }
        float* dst = g_dist + ((size_t)(b * N_ + i0 + r * 8 + ii) << 12) + j0 + c * 8;
        *(float4*)&dst[0] = *(float4*)&v[0];
        *(float4*)&dst[4] = *(float4*)&v[4];
    }

    // mirror store via staged transpose (off-diagonal tiles only).
    // Two rounds of 64 output-rows; stage[cc][i] pitch 129 (bank spread).
    // Values recomputed from live acc2 -> bitwise identical.
    if (bx != by) {
        #pragma unroll
        for (int p = 0; p < 2; p++) {
            __syncthreads();            // pool free (mainloop/prev round done)
            if ((c >> 3) == p) {
                int cl = (c & 7) * 8;   // stage row base for this thread
                #pragma unroll
                for (int ii = 0; ii < 8; ii++) {
                    float si = sqa[r * 8 + ii];
                    #pragma unroll
                    for (int q = 0; q < 4; q++) {
                        float dx = __uint_as_float((unsigned)acc2[ii][q]);
                        float dy = __uint_as_float((unsigned)(acc2[ii][q] >> 32));
                        float s0 = si + sqb[c * 8 + 2 * q];
                        float s1 = si + sqb[c * 8 + 2 * q + 1];
                        pool[(cl + 2 * q)     * 129 + r * 8 + ii] =
                            sqrtf(fmaxf(s0 - 2.0f * dx, 0.0f));
                        pool[(cl + 2 * q + 1) * 129 + r * 8 + ii] =
                            sqrtf(fmaxf(s1 - 2.0f * dy, 0.0f));
                    }
                }
            }
            __syncthreads();
            // copy out: row j0+64p+cc, cols i0..i0+127 (coalesced)
            int jbase = j0 + p * 64;
            #pragma unroll
            for (int k = 0; k < 32; k++) {
                int idx = t + k * 256;
                int cc = idx >> 7;
                int i  = idx & 127;
                g_dist[((size_t)(b * N_ + jbase + cc) << 12) + i0 + i] =
                    pool[cc * 129 + i];
            }
        }
    }
}

// ---------------------------------------------------------------------------
// 3) select — proven R6/R8 configuration (~116us): single launch, 16384
//    blocks. Threshold-filter (warp bitonic of lane minima), one atomic per
//    warp, exact 17-pass warp argmin on u64 keys (bits<<32)|j == lax.top_k.
//    BYTE-IDENTICAL to R11.
// ---------------------------------------------------------------------------
__global__ __launch_bounds__(256) void select_kernel(float* __restrict__ out_idx_f) {
    __shared__ unsigned long long buf[4096];
    __shared__ float wtau[8];
    __shared__ int cnt;

    int row = blockIdx.x;                      // b*4096 + i
    const float* src = g_dist + (size_t)row * N_;
    int t = threadIdx.x;
    int lane = t & 31, w = t >> 5;
    unsigned lmask_lt = (1u << lane) - 1u;

    if (t == 0) cnt = 0;

    float4 vv[4];
    #pragma unroll
    for (int u = 0; u < 4; u++)
        vv[u] = ((const float4*)src)[128 * w + lane + 32 * u];

    float mn;
    {
        float m0 = fminf(fminf(vv[0].x, vv[0].y), fminf(vv[0].z, vv[0].w));
        float m1 = fminf(fminf(vv[1].x, vv[1].y), fminf(vv[1].z, vv[1].w));
        float m2 = fminf(fminf(vv[2].x, vv[2].y), fminf(vv[2].z, vv[2].w));
        float m3 = fminf(fminf(vv[3].x, vv[3].y), fminf(vv[3].z, vv[3].w));
        mn = fminf(fminf(m0, m1), fminf(m2, m3));
    }

    float x = mn;
    #pragma unroll
    for (int k = 2; k <= 32; k <<= 1) {
        #pragma unroll
        for (int j2 = k >> 1; j2 > 0; j2 >>= 1) {
            float other = __shfl_xor_sync(0xffffffffu, x, j2);
            bool up    = ((lane & k) == 0);
            bool small = ((lane & j2) == 0);
            x = (small == up) ? fminf(x, other) : fmaxf(x, other);
        }
    }
    float tau_w = __shfl_sync(0xffffffffu, x, K_);
    if (lane == 0) wtau[w] = tau_w;
    __syncthreads();
    float tau = wtau[0];
    #pragma unroll
    for (int q = 1; q < 8; q++) tau = fminf(tau, wtau[q]);

    float    val[16];
    unsigned msk[16];
    int tot = 0;
    #pragma unroll
    for (int u = 0; u < 4; u++) {
        val[u * 4 + 0] = vv[u].x; val[u * 4 + 1] = vv[u].y;
        val[u * 4 + 2] = vv[u].z; val[u * 4 + 3] = vv[u].w;
    }
    #pragma unroll
    for (int e = 0; e < 16; e++) {
        msk[e] = __ballot_sync(0xffffffffu, val[e] <= tau);
        tot += __popc(msk[e]);
    }
    int wbase = 0;
    if (lane == 0) wbase = atomicAdd(&cnt, tot);
    wbase = __shfl_sync(0xffffffffu, wbase, 0);
    int off = 0;
    #pragma unroll
    for (int e = 0; e < 16; e++) {
        if (val[e] <= tau) {
            int j = (128 * w + lane + 32 * (e >> 2)) * 4 + (e & 3);
            buf[wbase + off + __popc(msk[e] & lmask_lt)] =
                ((unsigned long long)__float_as_uint(val[e]) << 32) | (unsigned)j;
        }
        off += __popc(msk[e]);
    }
    __syncthreads();

    if (w == 0) {
        int n = cnt;
        for (int p = 0; p <= K_; p++) {
            unsigned long long m = 0xFFFFFFFFFFFFFFFFull;
            for (int q = lane; q < n; q += 32) m = (buf[q] < m) ? buf[q] : m;
            #pragma unroll
            for (int o2 = 16; o2; o2 >>= 1) {
                unsigned long long o = __shfl_xor_sync(0xffffffffu, m, o2);
                m = (o < m) ? o : m;
            }
            for (int q = lane; q < n; q += 32)
                if (buf[q] == m) buf[q] = 0xFFFFFFFFFFFFFFFFull;
            if (lane == 0 && p > 0) {
                int j = (int)(m & 0xFFFFFFFFu);
                g_idx[row * K_ + (p - 1)]     = j;
                out_idx_f[row * K_ + (p - 1)] = (float)j;
            }
        }
    }
}

// ---------------------------------------------------------------------------
// 4) gather v3 (measured ~37us): smem-row gather. Block = (b, channel, octant).
// ---------------------------------------------------------------------------
__global__ __launch_bounds__(256) void gather_kernel(const float* __restrict__ pc,
                                                     float* __restrict__ out) {
    __shared__ float rowv[N_];

    int blk = blockIdx.x;            // 2048 blocks: b(2) | c(6) | s(3)
    int s   = blk & 7;
    int c   = (blk >> 3) & 63;
    int b   = blk >> 9;
    int t   = threadIdx.x;
    const float* src = pc + ((size_t)b * D_ + c) * N_;

    #pragma unroll
    for (int q = 0; q < 4; q++)
        ((float4*)rowv)[t + q * 256] = ((const float4*)src)[t + q * 256];
    __syncthreads();

    int n0 = s * 512;
    const int* idxp = g_idx + ((size_t)b * N_ + n0) * K_;
    size_t obase = (size_t)b * 2 * D_ * N_ * K_ + ((size_t)c * N_ + n0) * K_;
    float* oc = out + obase;
    float* on = out + obase + (size_t)D_ * N_ * K_;

    #pragma unroll 4
    for (int it = 0; it < 32; it++) {
        int l = t + it * 256;
        int n = l >> 4;
        int j = idxp[l];
        float ce = rowv[n0 + n];
        float nb = rowv[j];
        oc[l] = ce;
        on[l] = nb - ce;
    }
}

// ---------------------------------------------------------------------------
extern "C" void kernel_launch(void* const* d_in, const int* in_sizes, int n_in,
                              void* d_out, int out_size) {
    const float* pc = (const float*)d_in[0];
    float* out = (float*)d_out;
    float* out_idx = out + (size_t)B_ * 2 * D_ * N_ * K_;

    sq_kernel<<<(B_ * N_) / 256, 256>>>(pc);
    dim3 gg(528, 1, B_);                      // upper-triangle tiles
    d2_kernel<<<gg, 256>>>(pc);
    select_kernel<<<B_ * N_, 256>>>(out_idx);
    gather_kernel<<<B_ * D_ * 8, 256>>>(pc, out);
}